// round 15
// baseline (speedup 1.0000x reference)
#include <cuda_runtime.h>
#include <cuda_bf16.h>
#include <cooperative_groups.h>
#include <cstdint>
#include <cstring>

namespace cg = cooperative_groups;

#define DIM 64
#define NODES_MAX 100000
#define EDGES_MAX 1600000

// Allocation-free scratch (__device__ globals; zero-initialized at load).
// SELF-CLEANING: g_count / g_cursor are zero at entry of every invocation;
// gather phase re-zeroes g_count, fill phase re-zeroes g_cursor.
__device__ int            g_count[NODES_MAX];   // degree accumulator
__device__ int            g_start[NODES_MAX];   // CSR bucket starts (fill)
__device__ int2           g_sc[NODES_MAX];      // {start, count} (gather)
__device__ int            g_csr[EDGES_MAX];     // src per bucketed edge
__device__ unsigned short g_rank[EDGES_MAX];    // edge rank within bucket
__device__ int            g_cursor;             // global bucket allocator
__device__ float          g_agg[(size_t)NODES_MAX * DIM];  // h = x + sum
__device__ uint4          g_wbuf[2304];         // 36864B split-bf16 weights

#define STRIDE 144
#define A_HI_OFF 0
#define A_LO_OFF 18432
#define B1H_OFF  36864
#define B1L_OFF  46080
#define B2H_OFF  55296
#define B2L_OFF  64512
#define MLP_SMEM 73728

__device__ __forceinline__ uint32_t pack_bf(__nv_bfloat16 a, __nv_bfloat16 b) {
    __nv_bfloat162 t;
    t.x = a; t.y = b;
    uint32_t r;
    memcpy(&r, &t, 4);
    return r;
}

__device__ __forceinline__ void split2(float a, float b,
                                       uint32_t& hi, uint32_t& lo) {
    __nv_bfloat16 ah = __float2bfloat16_rn(a);
    __nv_bfloat16 bh = __float2bfloat16_rn(b);
    hi = pack_bf(ah, bh);
    lo = pack_bf(__float2bfloat16_rn(a - __bfloat162float(ah)),
                 __float2bfloat16_rn(b - __bfloat162float(bh)));
}

// ===========================================================================
// Cooperative build+gather: hist(+weight prep) -> scan -> fill -> gather,
// separated by grid.sync(). Grid-stride everywhere; no SMEM pressure, so
// full occupancy in every phase.
// ===========================================================================
__global__ __launch_bounds__(256) void build_gather_kernel(
        const int* __restrict__ dst, const int* __restrict__ src,
        const float* __restrict__ x,
        const float* __restrict__ W1, const float* __restrict__ W2,
        int E, int N) {
    cg::grid_group grid = cg::this_grid();
    const int tid    = threadIdx.x;
    const int gtid   = blockIdx.x * 256 + tid;
    const int gsz    = gridDim.x * 256;
    const int lane   = tid & 31;
    const int wid    = tid >> 5;

    // ---------- Phase 1: histogram + (blocks 0..3) weight prep ----------
    if (blockIdx.x < 4 && tid < 64) {
        const int part = blockIdx.x;            // 0=B1H,1=B1L,2=B2H,3=B2L
        const int n    = tid;
        const float* W = (part < 2) ? W1 : W2;
        const bool lo  = part & 1;
        char* dstp = (char*)g_wbuf + part * 9216 + n * STRIDE;
        #pragma unroll
        for (int q = 0; q < 8; q++) {
            uint32_t words[4];
            #pragma unroll
            for (int p = 0; p < 4; p++) {
                float v0 = __ldg(&W[(q * 8 + p * 2) * 64 + n]);
                float v1 = __ldg(&W[(q * 8 + p * 2 + 1) * 64 + n]);
                uint32_t hi, lw;
                split2(v0, v1, hi, lw);
                words[p] = lo ? lw : hi;
            }
            ((uint4*)dstp)[q] = make_uint4(words[0], words[1], words[2], words[3]);
        }
    }
    for (int i = gtid; i < E; i += gsz) {
        g_rank[i] = (unsigned short)atomicAdd(&g_count[dst[i]], 1);
    }
    grid.sync();

    // ---------- Phase 2: scan (virtual 256-wide blocks) ----------
    {
        __shared__ int wsum[8];
        __shared__ int base_sh;
        for (int vb = blockIdx.x; vb * 256 < N; vb += gridDim.x) {
            int i = vb * 256 + tid;
            int v = (i < N) ? g_count[i] : 0;
            int s = v;
            #pragma unroll
            for (int off = 1; off < 32; off <<= 1) {
                int u = __shfl_up_sync(0xffffffffu, s, off);
                if (lane >= off) s += u;
            }
            if (lane == 31) wsum[wid] = s;
            __syncthreads();
            if (wid == 0) {
                int ws = (lane < 8) ? wsum[lane] : 0;
                #pragma unroll
                for (int off = 1; off < 8; off <<= 1) {
                    int u = __shfl_up_sync(0xffffffffu, ws, off);
                    if (lane >= off) ws += u;
                }
                if (lane < 8) wsum[lane] = ws;
                if (lane == 7) base_sh = atomicAdd(&g_cursor, ws);
            }
            __syncthreads();
            int woff = (wid == 0) ? 0 : wsum[wid - 1];
            if (i < N) {
                int st = base_sh + woff + s - v;
                g_start[i] = st;
                g_sc[i] = make_int2(st, v);
            }
            __syncthreads();   // wsum/base_sh reuse safety for next vb
        }
    }
    grid.sync();

    // ---------- Phase 3: fill (atomic-free) + cursor reset ----------
    if (gtid == 0) g_cursor = 0;
    for (int i = gtid; i < E; i += gsz) {
        g_csr[g_start[dst[i]] + (int)g_rank[i]] = src[i];
    }
    grid.sync();

    // ---------- Phase 4: gather (warp per node, grid-stride) ----------
    {
        const int c    = lane & 15;
        const int slot = lane >> 4;
        const int gwarp  = gtid >> 5;
        const int nwarps = gsz >> 5;
        const float4* x4 = (const float4*)x;

        for (int n = gwarp; n < N; n += nwarps) {
            const int2 sc = __ldg(&g_sc[n]);
            const int s = sc.x;
            const int e = s + sc.y;
            if (lane == 0) g_count[n] = 0;   // restore zero invariant

            float4 a = make_float4(0.f, 0.f, 0.f, 0.f);
            int j = s + slot;
            for (; j + 2 < e; j += 4) {
                int nb0 = __ldg(&g_csr[j]);
                int nb1 = __ldg(&g_csr[j + 2]);
                float4 v0 = __ldg(&x4[(size_t)nb0 * 16 + c]);
                float4 v1 = __ldg(&x4[(size_t)nb1 * 16 + c]);
                a.x += v0.x + v1.x;
                a.y += v0.y + v1.y;
                a.z += v0.z + v1.z;
                a.w += v0.w + v1.w;
            }
            if (j < e) {
                int nb = __ldg(&g_csr[j]);
                float4 v = __ldg(&x4[(size_t)nb * 16 + c]);
                a.x += v.x; a.y += v.y; a.z += v.z; a.w += v.w;
            }

            a.x += __shfl_xor_sync(0xffffffffu, a.x, 16);
            a.y += __shfl_xor_sync(0xffffffffu, a.y, 16);
            a.z += __shfl_xor_sync(0xffffffffu, a.z, 16);
            a.w += __shfl_xor_sync(0xffffffffu, a.w, 16);

            if (slot == 0) {
                float4 xv = x4[(size_t)n * 16 + c];
                ((float4*)g_agg)[(size_t)n * 16 + c] =
                    make_float4(xv.x + a.x, xv.y + a.y, xv.z + a.z, xv.w + a.w);
            }
        }
    }
}

// ===========================================================================
// Tensor-core MLP (mma.sync m16n8k16 bf16, split precision). Unchanged.
// ===========================================================================
__device__ __forceinline__ uint32_t smem_u32(const void* p) {
    uint32_t a;
    asm("{ .reg .u64 t; cvta.to.shared.u64 t, %1; cvt.u32.u64 %0, t; }"
        : "=r"(a) : "l"(p));
    return a;
}

__device__ __forceinline__ void ldm4(uint32_t* f, uint32_t addr) {
    asm volatile("ldmatrix.sync.aligned.m8n8.x4.shared.b16 {%0,%1,%2,%3}, [%4];"
                 : "=r"(f[0]), "=r"(f[1]), "=r"(f[2]), "=r"(f[3]) : "r"(addr));
}

__device__ __forceinline__ void mma16816(float* d, const uint32_t* a,
                                         uint32_t b0, uint32_t b1) {
    asm volatile(
        "mma.sync.aligned.m16n8k16.row.col.f32.bf16.bf16.f32 "
        "{%0,%1,%2,%3}, {%4,%5,%6,%7}, {%8,%9}, {%0,%1,%2,%3};"
        : "+f"(d[0]), "+f"(d[1]), "+f"(d[2]), "+f"(d[3])
        : "r"(a[0]), "r"(a[1]), "r"(a[2]), "r"(a[3]), "r"(b0), "r"(b1));
}

__global__ __launch_bounds__(256) void mlp_tc_kernel(const float* __restrict__ x,
                                                     const float* __restrict__ b1,
                                                     const float* __restrict__ b2,
                                                     float* __restrict__ out,
                                                     int N) {
    extern __shared__ char sm[];
    const uint32_t sbase = smem_u32(sm);
    const int tid  = threadIdx.x;
    const int node0 = blockIdx.x * 128;

    for (int i = tid; i < 2048; i += 256) {
        int m  = i >> 4;
        int f4 = i & 15;
        int node = node0 + m;
        float4 v = (node < N) ? ((const float4*)g_agg)[(size_t)node * 16 + f4]
                              : make_float4(0.f, 0.f, 0.f, 0.f);
        uint32_t h0, l0, h1, l1;
        split2(v.x, v.y, h0, l0);
        split2(v.z, v.w, h1, l1);
        uint32_t off = (uint32_t)m * STRIDE + (uint32_t)f4 * 8;
        *(uint2*)(sm + A_HI_OFF + off) = make_uint2(h0, h1);
        *(uint2*)(sm + A_LO_OFF + off) = make_uint2(l0, l1);
    }

    for (int i = tid; i < 2304; i += 256) {
        ((uint4*)(sm + B1H_OFF))[i] = g_wbuf[i];
    }
    __syncthreads();

    const int w    = tid >> 5;
    const int lane = tid & 31;
    const int g    = lane >> 2;
    const int t    = lane & 3;
    const int q    = lane >> 3;
    const int r    = lane & 7;

    const uint32_t aoff = (uint32_t)(w * 16 + (q & 1) * 8 + r) * STRIDE
                        + (uint32_t)(q >> 1) * 16;
    const uint32_t boff0 = (uint32_t)((q >> 1) * 8 + r) * STRIDE
                         + (uint32_t)(q & 1) * 16;

    float acc1[8][4];
    #pragma unroll
    for (int n = 0; n < 8; n++)
        #pragma unroll
        for (int j = 0; j < 4; j++) acc1[n][j] = 0.f;

    #pragma unroll
    for (int kk = 0; kk < 4; kk++) {
        uint32_t ah[4], al[4];
        ldm4(ah, sbase + A_HI_OFF + aoff + kk * 32);
        ldm4(al, sbase + A_LO_OFF + aoff + kk * 32);
        #pragma unroll
        for (int p = 0; p < 4; p++) {
            uint32_t bo = boff0 + (uint32_t)p * 16 * STRIDE + kk * 32;
            uint32_t bh[4], bl[4];
            ldm4(bh, sbase + B1H_OFF + bo);
            ldm4(bl, sbase + B1L_OFF + bo);
            mma16816(acc1[2 * p],     ah, bh[0], bh[1]);
            mma16816(acc1[2 * p],     ah, bl[0], bl[1]);
            mma16816(acc1[2 * p],     al, bh[0], bh[1]);
            mma16816(acc1[2 * p + 1], ah, bh[2], bh[3]);
            mma16816(acc1[2 * p + 1], ah, bl[2], bl[3]);
            mma16816(acc1[2 * p + 1], al, bh[2], bh[3]);
        }
    }

    float acc2[8][4];
    #pragma unroll
    for (int n = 0; n < 8; n++)
        #pragma unroll
        for (int j = 0; j < 4; j++) acc2[n][j] = 0.f;

    #pragma unroll
    for (int kk = 0; kk < 4; kk++) {
        uint32_t ah[4], al[4];
        {
            int nt = 2 * kk;
            float bb0 = __ldg(&b1[nt * 8 + 2 * t]);
            float bb1 = __ldg(&b1[nt * 8 + 2 * t + 1]);
            split2(fmaxf(acc1[nt][0] + bb0, 0.f),
                   fmaxf(acc1[nt][1] + bb1, 0.f), ah[0], al[0]);
            split2(fmaxf(acc1[nt][2] + bb0, 0.f),
                   fmaxf(acc1[nt][3] + bb1, 0.f), ah[1], al[1]);
            nt = 2 * kk + 1;
            bb0 = __ldg(&b1[nt * 8 + 2 * t]);
            bb1 = __ldg(&b1[nt * 8 + 2 * t + 1]);
            split2(fmaxf(acc1[nt][0] + bb0, 0.f),
                   fmaxf(acc1[nt][1] + bb1, 0.f), ah[2], al[2]);
            split2(fmaxf(acc1[nt][2] + bb0, 0.f),
                   fmaxf(acc1[nt][3] + bb1, 0.f), ah[3], al[3]);
        }
        #pragma unroll
        for (int p = 0; p < 4; p++) {
            uint32_t bo = boff0 + (uint32_t)p * 16 * STRIDE + kk * 32;
            uint32_t bh[4], bl[4];
            ldm4(bh, sbase + B2H_OFF + bo);
            ldm4(bl, sbase + B2L_OFF + bo);
            mma16816(acc2[2 * p],     ah, bh[0], bh[1]);
            mma16816(acc2[2 * p],     ah, bl[0], bl[1]);
            mma16816(acc2[2 * p],     al, bh[0], bh[1]);
            mma16816(acc2[2 * p + 1], ah, bh[2], bh[3]);
            mma16816(acc2[2 * p + 1], ah, bl[2], bl[3]);
            mma16816(acc2[2 * p + 1], al, bh[2], bh[3]);
        }
    }

    const int nodeA = node0 + w * 16 + g;
    const int nodeB = nodeA + 8;
    #pragma unroll
    for (int nt = 0; nt < 8; nt++) {
        int col = nt * 8 + 2 * t;
        float bb0 = __ldg(&b2[col]);
        float bb1 = __ldg(&b2[col + 1]);
        if (nodeA < N) {
            const float2 xv = *(const float2*)&x[(size_t)nodeA * 64 + col];
            float2 o;
            o.x = xv.x + fmaxf(acc2[nt][0] + bb0, 0.f);
            o.y = xv.y + fmaxf(acc2[nt][1] + bb1, 0.f);
            *(float2*)&out[(size_t)nodeA * 64 + col] = o;
        }
        if (nodeB < N) {
            const float2 xv = *(const float2*)&x[(size_t)nodeB * 64 + col];
            float2 o;
            o.x = xv.x + fmaxf(acc2[nt][2] + bb0, 0.f);
            o.y = xv.y + fmaxf(acc2[nt][3] + bb1, 0.f);
            *(float2*)&out[(size_t)nodeB * 64 + col] = o;
        }
    }
}

// ===========================================================================
// Launch (2 kernels: cooperative build+gather, then MLP)
// ===========================================================================
extern "C" void kernel_launch(void* const* d_in, const int* in_sizes, int n_in,
                              void* d_out, int out_size) {
    const float* x   = (const float*)d_in[0];
    const int*   ei  = (const int*)d_in[1];
    const float* W1  = (const float*)d_in[2];
    const float* b1  = (const float*)d_in[3];
    const float* W2  = (const float*)d_in[4];
    const float* b2  = (const float*)d_in[5];
    float* out = (float*)d_out;

    int N = in_sizes[0] / DIM;       // 100000
    int E = in_sizes[1] / 2;         // 1600000
    const int* src = (const int*)ei;
    const int* dst = (const int*)ei + E;

    static int coop_blocks = 0;
    if (coop_blocks == 0) {
        cudaFuncSetAttribute(mlp_tc_kernel,
                             cudaFuncAttributeMaxDynamicSharedMemorySize,
                             MLP_SMEM);
        int dev = 0;
        cudaGetDevice(&dev);
        int sms = 0;
        cudaDeviceGetAttribute(&sms, cudaDevAttrMultiProcessorCount, dev);
        int per_sm = 0;
        cudaOccupancyMaxActiveBlocksPerMultiprocessor(&per_sm,
                                                      build_gather_kernel,
                                                      256, 0);
        coop_blocks = sms * per_sm;
    }

    void* args[] = {(void*)&dst, (void*)&src, (void*)&x,
                    (void*)&W1, (void*)&W2, (void*)&E, (void*)&N};
    cudaLaunchCooperativeKernel((void*)build_gather_kernel,
                                dim3(coop_blocks), dim3(256), args, 0, 0);

    mlp_tc_kernel<<<(N + 127) / 128, 256, MLP_SMEM>>>(x, b1, b2, out, N);
}

// round 17
// speedup vs baseline: 1.3200x; 1.3200x over previous
#include <cuda_runtime.h>
#include <cuda_bf16.h>
#include <cstdint>
#include <cstring>

#define DIM 64
#define NODES_MAX 100000
#define EDGES_MAX 1600000

// Allocation-free scratch (__device__ globals; zero-initialized at load).
// SELF-CLEANING INVARIANT: g_count and g_cursor are zero at the start of
// every kernel_launch invocation. gather re-zeroes g_count after consuming
// it; fill re-zeroes g_cursor after scan consumed it.
__device__ int            g_count[NODES_MAX];   // degree accumulator
__device__ int            g_start[NODES_MAX];   // CSR bucket starts (fill)
__device__ int2           g_sc[NODES_MAX];      // {start, count} (gather)
__device__ int            g_csr[EDGES_MAX];     // src per bucketed edge
__device__ unsigned short g_rank[EDGES_MAX];    // edge rank within bucket
__device__ int            g_cursor;             // global bucket allocator
__device__ float          g_agg[(size_t)NODES_MAX * DIM];  // h = x + sum
// B fragments in mma lane order: [part(4)][kk(4)][p(4)][lane(32)] uint4,
// part: 0=L1 hi, 1=L1 lo, 2=L2 hi, 3=L2 lo.  32 KB total, L1/L2-resident.
__device__ uint4          g_wfrag[4 * 4 * 4 * 32];

#define STRIDE 144
#define A_HI_OFF 0
#define A_LO_OFF 18432
#define MLP_SMEM 36864   // A tiles only; B comes from g_wfrag

__device__ __forceinline__ uint32_t pack_bf(__nv_bfloat16 a, __nv_bfloat16 b) {
    __nv_bfloat162 t;
    t.x = a; t.y = b;
    uint32_t r;
    memcpy(&r, &t, 4);
    return r;
}

__device__ __forceinline__ void split2(float a, float b,
                                       uint32_t& hi, uint32_t& lo) {
    __nv_bfloat16 ah = __float2bfloat16_rn(a);
    __nv_bfloat16 bh = __float2bfloat16_rn(b);
    hi = pack_bf(ah, bh);
    lo = pack_bf(__float2bfloat16_rn(a - __bfloat162float(ah)),
                 __float2bfloat16_rn(b - __bfloat162float(bh)));
}

__device__ __forceinline__ uint32_t smem_u32(const void* p) {
    uint32_t a;
    asm("{ .reg .u64 t; cvta.to.shared.u64 t, %1; cvt.u32.u64 %0, t; }"
        : "=r"(a) : "l"(p));
    return a;
}

__device__ __forceinline__ void ldm4(uint32_t* f, uint32_t addr) {
    asm volatile("ldmatrix.sync.aligned.m8n8.x4.shared.b16 {%0,%1,%2,%3}, [%4];"
                 : "=r"(f[0]), "=r"(f[1]), "=r"(f[2]), "=r"(f[3]) : "r"(addr));
}

__device__ __forceinline__ void mma16816(float* d, const uint32_t* a,
                                         uint32_t b0, uint32_t b1) {
    asm volatile(
        "mma.sync.aligned.m16n8k16.row.col.f32.bf16.bf16.f32 "
        "{%0,%1,%2,%3}, {%4,%5,%6,%7}, {%8,%9}, {%0,%1,%2,%3};"
        : "+f"(d[0]), "+f"(d[1]), "+f"(d[2]), "+f"(d[3])
        : "r"(a[0]), "r"(a[1]), "r"(a[2]), "r"(a[3]), "r"(b0), "r"(b1));
}

// ===========================================================================
// 1. histogram of dst; returned old value IS the edge's bucket rank (u16)
// ===========================================================================
__global__ __launch_bounds__(256) void hist_kernel(const int* __restrict__ dst,
                                                   int E) {
    int i = blockIdx.x * 256 + threadIdx.x;
    if (i < E) g_rank[i] = (unsigned short)atomicAdd(&g_count[dst[i]], 1);
}

// ===========================================================================
// 2. one-pass scan (warp-shuffle) + weight-fragment prep in the LAST block.
// Prep: stage split-bf16 weight image (144B-stride ldmatrix layout) in a
// 16B-ALIGNED SMEM buffer (uint4 array — char[] caused the round-16
// misaligned-address crash), then warp 0 extracts per-lane B fragments via
// the same ldmatrix path the MLP used before, storing them to g_wfrag.
// ===========================================================================
__global__ __launch_bounds__(1024) void scan_prep_kernel(
        int N, int nb,
        const float* __restrict__ W1, const float* __restrict__ W2) {
    __shared__ int   wsum[32];
    __shared__ int   base_sh;
    __shared__ uint4 wsm4[36864 / 16];   // 16B-aligned staging buffer

    const int t = threadIdx.x;
    char* wsm = (char*)wsm4;

    if (blockIdx.x == (unsigned)nb) {
        // ---- weight prep ----
        if (t < 256) {
            const int part = t >> 6;             // 0=L1H,1=L1L,2=L2H,3=L2L
            const int n    = t & 63;
            const float* W = (part < 2) ? W1 : W2;
            const bool lo  = part & 1;
            char* dstp = wsm + part * 9216 + n * STRIDE;
            #pragma unroll
            for (int qq = 0; qq < 8; qq++) {
                uint32_t words[4];
                #pragma unroll
                for (int p = 0; p < 4; p++) {
                    float v0 = __ldg(&W[(qq * 8 + p * 2) * 64 + n]);
                    float v1 = __ldg(&W[(qq * 8 + p * 2 + 1) * 64 + n]);
                    uint32_t hi, lw;
                    split2(v0, v1, hi, lw);
                    words[p] = lo ? lw : hi;
                }
                ((uint4*)dstp)[qq] =
                    make_uint4(words[0], words[1], words[2], words[3]);
            }
        }
        __syncthreads();
        if (t < 32) {
            const int lane = t;
            const int q = lane >> 3;
            const int r = lane & 7;
            const uint32_t sb = smem_u32(wsm);
            const uint32_t boff0 = (uint32_t)((q >> 1) * 8 + r) * STRIDE
                                 + (uint32_t)(q & 1) * 16;
            for (int part = 0; part < 4; part++) {
                for (int kk = 0; kk < 4; kk++) {
                    for (int p = 0; p < 4; p++) {
                        uint32_t f[4];
                        ldm4(f, sb + part * 9216 + boff0
                                + (uint32_t)p * 16 * STRIDE + kk * 32);
                        g_wfrag[((part * 4 + kk) * 4 + p) * 32 + lane] =
                            make_uint4(f[0], f[1], f[2], f[3]);
                    }
                }
            }
        }
        return;
    }

    // ---- scan ----
    const int lane = t & 31;
    const int wid  = t >> 5;
    const int i    = blockIdx.x * 1024 + t;
    const int v    = (i < N) ? g_count[i] : 0;

    int s = v;
    #pragma unroll
    for (int off = 1; off < 32; off <<= 1) {
        int u = __shfl_up_sync(0xffffffffu, s, off);
        if (lane >= off) s += u;
    }
    if (lane == 31) wsum[wid] = s;
    __syncthreads();
    if (wid == 0) {
        int ws = wsum[lane];
        #pragma unroll
        for (int off = 1; off < 32; off <<= 1) {
            int u = __shfl_up_sync(0xffffffffu, ws, off);
            if (lane >= off) ws += u;
        }
        wsum[lane] = ws;
        if (lane == 31) base_sh = atomicAdd(&g_cursor, ws);
    }
    __syncthreads();
    int woff = (wid == 0) ? 0 : wsum[wid - 1];
    if (i < N) {
        int st = base_sh + woff + s - v;
        g_start[i] = st;
        g_sc[i] = make_int2(st, v);
    }
}

// ===========================================================================
// 3. atomic-free fill: pos = start[dst] + rank; resets g_cursor.
// ===========================================================================
__global__ __launch_bounds__(256) void fill_kernel(const int* __restrict__ src,
                                                   const int* __restrict__ dst,
                                                   int E) {
    int i = blockIdx.x * 256 + threadIdx.x;
    if (i == 0) g_cursor = 0;
    if (i < E) {
        g_csr[g_start[dst[i]] + (int)g_rank[i]] = src[i];
    }
}

// ===========================================================================
// 4. pull-gather: one warp per node (16 lanes x 2 slots, 4 loads in flight).
// Re-zeroes g_count for the next invocation.
// ===========================================================================
__global__ __launch_bounds__(256) void gather_kernel(const float* __restrict__ x,
                                                     int N) {
    int warp = (blockIdx.x * blockDim.x + threadIdx.x) >> 5;
    if (warp >= N) return;
    const int lane = threadIdx.x & 31;
    const int c    = lane & 15;
    const int slot = lane >> 4;

    const float4* x4 = (const float4*)x;
    const int n = warp;
    const int2 sc = __ldg(&g_sc[n]);
    const int s = sc.x;
    const int e = s + sc.y;

    if (lane == 0) g_count[n] = 0;   // restore zero invariant

    float4 a = make_float4(0.f, 0.f, 0.f, 0.f);
    int j = s + slot;
    for (; j + 2 < e; j += 4) {
        int nb0 = __ldg(&g_csr[j]);
        int nb1 = __ldg(&g_csr[j + 2]);
        float4 v0 = __ldg(&x4[(size_t)nb0 * 16 + c]);
        float4 v1 = __ldg(&x4[(size_t)nb1 * 16 + c]);
        a.x += v0.x + v1.x;
        a.y += v0.y + v1.y;
        a.z += v0.z + v1.z;
        a.w += v0.w + v1.w;
    }
    if (j < e) {
        int nb = __ldg(&g_csr[j]);
        float4 v = __ldg(&x4[(size_t)nb * 16 + c]);
        a.x += v.x; a.y += v.y; a.z += v.z; a.w += v.w;
    }

    a.x += __shfl_xor_sync(0xffffffffu, a.x, 16);
    a.y += __shfl_xor_sync(0xffffffffu, a.y, 16);
    a.z += __shfl_xor_sync(0xffffffffu, a.z, 16);
    a.w += __shfl_xor_sync(0xffffffffu, a.w, 16);

    if (slot == 0) {
        float4 xv = x4[(size_t)n * 16 + c];
        ((float4*)g_agg)[(size_t)n * 16 + c] =
            make_float4(xv.x + a.x, xv.y + a.y, xv.z + a.z, xv.w + a.w);
    }
}

// ===========================================================================
// 5. Tensor-core MLP (mma.sync m16n8k16 bf16, split precision).
// A tiles in SMEM (ldmatrix); B fragments loaded per-lane from g_wfrag
// (coalesced LDG.128, L1-resident). 3 blocks/SM via __launch_bounds__.
// ===========================================================================
__global__ __launch_bounds__(256, 3) void mlp_tc_kernel(
        const float* __restrict__ x,
        const float* __restrict__ b1,
        const float* __restrict__ b2,
        float* __restrict__ out, int N) {
    extern __shared__ char sm[];
    const uint32_t sbase = smem_u32(sm);
    const int tid  = threadIdx.x;
    const int node0 = blockIdx.x * 128;

    // stage A: split-bf16 h tile from g_agg
    for (int i = tid; i < 2048; i += 256) {
        int m  = i >> 4;
        int f4 = i & 15;
        int node = node0 + m;
        float4 v = (node < N) ? ((const float4*)g_agg)[(size_t)node * 16 + f4]
                              : make_float4(0.f, 0.f, 0.f, 0.f);
        uint32_t h0, l0, h1, l1;
        split2(v.x, v.y, h0, l0);
        split2(v.z, v.w, h1, l1);
        uint32_t off = (uint32_t)m * STRIDE + (uint32_t)f4 * 8;
        *(uint2*)(sm + A_HI_OFF + off) = make_uint2(h0, h1);
        *(uint2*)(sm + A_LO_OFF + off) = make_uint2(l0, l1);
    }
    __syncthreads();

    const int w    = tid >> 5;
    const int lane = tid & 31;
    const int g    = lane >> 2;
    const int t    = lane & 3;
    const int q    = lane >> 3;
    const int r    = lane & 7;

    const uint32_t aoff = (uint32_t)(w * 16 + (q & 1) * 8 + r) * STRIDE
                        + (uint32_t)(q >> 1) * 16;

    float acc1[8][4];
    #pragma unroll
    for (int n = 0; n < 8; n++)
        #pragma unroll
        for (int j = 0; j < 4; j++) acc1[n][j] = 0.f;

    #pragma unroll
    for (int kk = 0; kk < 4; kk++) {
        uint32_t ah[4], al[4];
        ldm4(ah, sbase + A_HI_OFF + aoff + kk * 32);
        ldm4(al, sbase + A_LO_OFF + aoff + kk * 32);
        #pragma unroll
        for (int p = 0; p < 4; p++) {
            uint4 bh = __ldg(&g_wfrag[((0 * 4 + kk) * 4 + p) * 32 + lane]);
            uint4 bl = __ldg(&g_wfrag[((1 * 4 + kk) * 4 + p) * 32 + lane]);
            mma16816(acc1[2 * p],     ah, bh.x, bh.y);
            mma16816(acc1[2 * p],     ah, bl.x, bl.y);
            mma16816(acc1[2 * p],     al, bh.x, bh.y);
            mma16816(acc1[2 * p + 1], ah, bh.z, bh.w);
            mma16816(acc1[2 * p + 1], ah, bl.z, bl.w);
            mma16816(acc1[2 * p + 1], al, bh.z, bh.w);
        }
    }

    float acc2[8][4];
    #pragma unroll
    for (int n = 0; n < 8; n++)
        #pragma unroll
        for (int j = 0; j < 4; j++) acc2[n][j] = 0.f;

    #pragma unroll
    for (int kk = 0; kk < 4; kk++) {
        uint32_t ah[4], al[4];
        {
            int nt = 2 * kk;
            float bb0 = __ldg(&b1[nt * 8 + 2 * t]);
            float bb1 = __ldg(&b1[nt * 8 + 2 * t + 1]);
            split2(fmaxf(acc1[nt][0] + bb0, 0.f),
                   fmaxf(acc1[nt][1] + bb1, 0.f), ah[0], al[0]);
            split2(fmaxf(acc1[nt][2] + bb0, 0.f),
                   fmaxf(acc1[nt][3] + bb1, 0.f), ah[1], al[1]);
            nt = 2 * kk + 1;
            bb0 = __ldg(&b1[nt * 8 + 2 * t]);
            bb1 = __ldg(&b1[nt * 8 + 2 * t + 1]);
            split2(fmaxf(acc1[nt][0] + bb0, 0.f),
                   fmaxf(acc1[nt][1] + bb1, 0.f), ah[2], al[2]);
            split2(fmaxf(acc1[nt][2] + bb0, 0.f),
                   fmaxf(acc1[nt][3] + bb1, 0.f), ah[3], al[3]);
        }
        #pragma unroll
        for (int p = 0; p < 4; p++) {
            uint4 bh = __ldg(&g_wfrag[((2 * 4 + kk) * 4 + p) * 32 + lane]);
            uint4 bl = __ldg(&g_wfrag[((3 * 4 + kk) * 4 + p) * 32 + lane]);
            mma16816(acc2[2 * p],     ah, bh.x, bh.y);
            mma16816(acc2[2 * p],     ah, bl.x, bl.y);
            mma16816(acc2[2 * p],     al, bh.x, bh.y);
            mma16816(acc2[2 * p + 1], ah, bh.z, bh.w);
            mma16816(acc2[2 * p + 1], ah, bl.z, bl.w);
            mma16816(acc2[2 * p + 1], al, bh.z, bh.w);
        }
    }

    const int nodeA = node0 + w * 16 + g;
    const int nodeB = nodeA + 8;
    #pragma unroll
    for (int nt = 0; nt < 8; nt++) {
        int col = nt * 8 + 2 * t;
        float bb0 = __ldg(&b2[col]);
        float bb1 = __ldg(&b2[col + 1]);
        if (nodeA < N) {
            const float2 xv = *(const float2*)&x[(size_t)nodeA * 64 + col];
            float2 o;
            o.x = xv.x + fmaxf(acc2[nt][0] + bb0, 0.f);
            o.y = xv.y + fmaxf(acc2[nt][1] + bb1, 0.f);
            *(float2*)&out[(size_t)nodeA * 64 + col] = o;
        }
        if (nodeB < N) {
            const float2 xv = *(const float2*)&x[(size_t)nodeB * 64 + col];
            float2 o;
            o.x = xv.x + fmaxf(acc2[nt][2] + bb0, 0.f);
            o.y = xv.y + fmaxf(acc2[nt][3] + bb1, 0.f);
            *(float2*)&out[(size_t)nodeB * 64 + col] = o;
        }
    }
}

// ===========================================================================
// Launch (5 kernels)
// ===========================================================================
extern "C" void kernel_launch(void* const* d_in, const int* in_sizes, int n_in,
                              void* d_out, int out_size) {
    const float* x   = (const float*)d_in[0];
    const int*   ei  = (const int*)d_in[1];
    const float* W1  = (const float*)d_in[2];
    const float* b1  = (const float*)d_in[3];
    const float* W2  = (const float*)d_in[4];
    const float* b2  = (const float*)d_in[5];
    float* out = (float*)d_out;

    int N = in_sizes[0] / DIM;       // 100000
    int E = in_sizes[1] / 2;         // 1600000
    const int* src = ei;
    const int* dst = ei + E;

    int EB = (E + 255) / 256;
    int nb = (N + 1023) / 1024;

    hist_kernel<<<EB, 256>>>(dst, E);
    scan_prep_kernel<<<nb + 1, 1024>>>(N, nb, W1, W2);
    fill_kernel<<<EB, 256>>>(src, dst, E);
    gather_kernel<<<(N * 32 + 255) / 256, 256>>>(x, N);

    static bool smem_set = false;
    if (!smem_set) {
        cudaFuncSetAttribute(mlp_tc_kernel,
                             cudaFuncAttributeMaxDynamicSharedMemorySize,
                             MLP_SMEM);
        smem_set = true;
    }
    mlp_tc_kernel<<<(N + 127) / 128, 256, MLP_SMEM>>>(x, b1, b2, out, N);
}